// round 10
// baseline (speedup 1.0000x reference)
#include <cuda_runtime.h>

// GCN_12867722019091 — 2-layer GCN, N=50000, E=800000, HID=64, OUT=2.
// Rank-1 layer-1 + linear propagation => per-edge work reduces to scalar /
// float2 scatter-adds. Single persistent kernel, 5 software grid barriers.
// R9 hardening: __launch_bounds__(256,4) guarantees co-residency (the R8/R9
// hang was almost certainly regs>64 -> 2 blocks/SM -> barrier deadlock).

constexpr int NN  = 50000;
constexpr int NE  = 800000;
constexpr int HID = 64;

constexpr int TB       = 256;
constexpr int NBLK_MAX = 592;           // 4 blocks/SM on 148 SMs

__device__ int    g_deg[NN];
__device__ float  g_dinv[NN];
__device__ float  g_p[NN];      // x[n] * dinv[n]
__device__ float  g_s1[NN];     // layer-1 scalar scatter accumulator
__device__ float2 g_p2[NN];     // g[n,:] * dinv[n]
__device__ float2 g_acc[NN];    // layer-2 float2 scatter accumulator

// grid barrier state (zero-init; g_count self-resets, g_sense monotonic)
__device__ unsigned g_count;
__device__ volatile unsigned g_sense;

// Sense-reversing grid barrier; arrival count = gridDim.x (runtime).
__device__ __forceinline__ void gsync(unsigned target) {
    __syncthreads();
    if (threadIdx.x == 0) {
        __threadfence();
        if (atomicAdd(&g_count, 1) == gridDim.x - 1) {
            g_count = 0;
            __threadfence();
            g_sense = target;                      // release
        } else {
            while ((int)(g_sense - target) < 0) { __nanosleep(64); }
            __threadfence();
        }
    }
    __syncthreads();
}

__global__ void __launch_bounds__(TB, 4) gcn_fused(
    const float* __restrict__ x,
    const int*   __restrict__ row,
    const int*   __restrict__ col,
    const float* __restrict__ W1,
    const float* __restrict__ b1,
    const float* __restrict__ W2,
    const float* __restrict__ b2,
    float* __restrict__ out)
{
    __shared__ float sW1[HID], sb1[HID], sW2[HID * 2];
    __shared__ unsigned s_base;

    const int t       = threadIdx.x;
    const int tid     = blockIdx.x * TB + t;
    const int nthread = gridDim.x * TB;

    // per-launch barrier base: every block reads this BEFORE it can arrive at
    // barrier 1, and g_sense only advances after ALL blocks arrive -> race-free.
    if (t == 0) s_base = g_sense;
    if (t < HID)     { sW1[t] = W1[t]; sb1[t] = b1[t]; }
    if (t < HID * 2) { sW2[t] = W2[t]; }
    __syncthreads();
    const unsigned base = s_base;

    // ---- Phase A: in-degree count (scratch zeroed by prev run / load) ----
    for (int i = tid; i < NE; i += nthread)
        atomicAdd(&g_deg[col[i]], 1);
    gsync(base + 1);

    // ---- Phase B: dinv = rsqrt(deg+1); p = x*dinv ----
    for (int i = tid; i < NN; i += nthread) {
        float dinv = rsqrtf((float)(g_deg[i] + 1));
        g_dinv[i] = dinv;
        g_p[i]    = x[i] * dinv;
    }
    gsync(base + 2);

    // ---- Phase C: s1[c] += p[r] ----
    for (int i = tid; i < NE; i += nthread) {
        int r = row[i];
        int c = col[i];
        atomicAdd(&g_s1[c], __ldg(&g_p[r]));
    }
    gsync(base + 3);

    // ---- Phase D: s1 = dinv*(acc+p); h1 = relu(W1*s1+b1); p2 = (h1@W2)*dinv ----
    for (int i = tid; i < NN; i += nthread) {
        float dinv = g_dinv[i];
        float s1   = dinv * (g_s1[i] + g_p[i]);
        float a = 0.f, b = 0.f;
#pragma unroll 16
        for (int j = 0; j < HID; ++j) {
            float h = fmaxf(fmaf(sW1[j], s1, sb1[j]), 0.f);
            a = fmaf(h, sW2[2 * j],     a);
            b = fmaf(h, sW2[2 * j + 1], b);
        }
        g_p2[i] = make_float2(a * dinv, b * dinv);
    }
    gsync(base + 4);

    // ---- Phase E: acc[c] += p2[r] (float2 vector atomic) ----
    for (int i = tid; i < NE; i += nthread) {
        int r = row[i];
        int c = col[i];
        float2 v = *reinterpret_cast<const float2*>(&g_p2[r]);
        atomicAdd(&g_acc[c], v);
    }
    gsync(base + 5);

    // ---- Phase F: out = dinv*(acc+p2) + b2 ; reset scratch for next replay ----
    for (int i = tid; i < NN; i += nthread) {
        float dinv = g_dinv[i];
        float2 acc = g_acc[i];
        float2 p2  = g_p2[i];
        float2 o;
        o.x = fmaf(dinv, acc.x + p2.x, b2[0]);
        o.y = fmaf(dinv, acc.y + p2.y, b2[1]);
        reinterpret_cast<float2*>(out)[i] = o;

        g_deg[i] = 0;
        g_s1[i]  = 0.f;
        g_acc[i] = make_float2(0.f, 0.f);
    }
}

extern "C" void kernel_launch(void* const* d_in, const int* in_sizes, int n_in,
                              void* d_out, int out_size) {
    const float* x   = (const float*)d_in[0];
    const int*   ei  = (const int*)d_in[1];   // [2, NE]: row then col
    const float* W1  = (const float*)d_in[2];
    const float* b1  = (const float*)d_in[3];
    const float* W2  = (const float*)d_in[4];
    const float* b2  = (const float*)d_in[5];
    float* out = (float*)d_out;

    const int* row = ei;
    const int* col = ei + NE;

    // Belt-and-braces: never launch more blocks than can be co-resident.
    int nblk = NBLK_MAX;
    int dev = 0, nsm = 0, per_sm = 0;
    if (cudaGetDevice(&dev) == cudaSuccess &&
        cudaDeviceGetAttribute(&nsm, cudaDevAttrMultiProcessorCount, dev) == cudaSuccess &&
        cudaOccupancyMaxActiveBlocksPerMultiprocessor(&per_sm, gcn_fused, TB, 0) == cudaSuccess &&
        nsm > 0 && per_sm > 0) {
        int cap = nsm * per_sm;
        if (cap < nblk) nblk = cap;
    }

    gcn_fused<<<nblk, TB>>>(x, row, col, W1, b1, W2, b2, out);
}

// round 11
// speedup vs baseline: 1.1268x; 1.1268x over previous
#include <cuda_runtime.h>

// GCN_12867722019091 — 2-layer GCN, N=50000, E=800000, HID=64, OUT=2.
// Rank-1 layer-1 + linear propagation => per-edge work reduces to scalar /
// float2 scatter-adds. Single persistent kernel, 5 software grid barriers.
// R10 lesson: regs=61 capped the fused kernel at 4 blocks/SM (50% occ) and
// starved the latency-bound edge phases. Force 8 blocks/SM (32 regs); phase D
// spills a little to L1-local, which is negligible (50k nodes only).

constexpr int NN  = 50000;
constexpr int NE  = 800000;
constexpr int HID = 64;

constexpr int TB       = 256;
constexpr int NBLK_MAX = 1184;          // 8 blocks/SM on 148 SMs

__device__ int    g_deg[NN];
__device__ float  g_dinv[NN];
__device__ float  g_p[NN];      // x[n] * dinv[n]
__device__ float  g_s1[NN];     // layer-1 scalar scatter accumulator
__device__ float2 g_p2[NN];     // g[n,:] * dinv[n]
__device__ float2 g_acc[NN];    // layer-2 float2 scatter accumulator

// grid barrier state (zero-init; g_count self-resets, g_sense monotonic)
__device__ unsigned g_count;
__device__ volatile unsigned g_sense;

// Sense-reversing grid barrier; arrival count = gridDim.x (runtime).
__device__ __forceinline__ void gsync(unsigned target) {
    __syncthreads();
    if (threadIdx.x == 0) {
        __threadfence();
        if (atomicAdd(&g_count, 1) == gridDim.x - 1) {
            g_count = 0;
            __threadfence();
            g_sense = target;                      // release
        } else {
            while ((int)(g_sense - target) < 0) { __nanosleep(32); }
            __threadfence();
        }
    }
    __syncthreads();
}

__global__ void __launch_bounds__(TB, 8) gcn_fused(
    const float* __restrict__ x,
    const int*   __restrict__ row,
    const int*   __restrict__ col,
    const float* __restrict__ W1,
    const float* __restrict__ b1,
    const float* __restrict__ W2,
    const float* __restrict__ b2,
    float* __restrict__ out)
{
    __shared__ float sW1[HID], sb1[HID], sW2[HID * 2];
    __shared__ unsigned s_base;

    const int t       = threadIdx.x;
    const int tid     = blockIdx.x * TB + t;
    const int nthread = gridDim.x * TB;

    // per-launch barrier base: every block reads this BEFORE it can arrive at
    // barrier 1, and g_sense only advances after ALL blocks arrive -> race-free.
    if (t == 0) s_base = g_sense;
    if (t < HID)     { sW1[t] = W1[t]; sb1[t] = b1[t]; }
    if (t < HID * 2) { sW2[t] = W2[t]; }
    __syncthreads();
    const unsigned base = s_base;

    // ---- Phase A: in-degree count (scratch zeroed by prev run / load) ----
#pragma unroll 2
    for (int i = tid; i < NE; i += nthread)
        atomicAdd(&g_deg[col[i]], 1);
    gsync(base + 1);

    // ---- Phase B: dinv = rsqrt(deg+1); p = x*dinv ----
    for (int i = tid; i < NN; i += nthread) {
        float dinv = rsqrtf((float)(g_deg[i] + 1));
        g_dinv[i] = dinv;
        g_p[i]    = x[i] * dinv;
    }
    gsync(base + 2);

    // ---- Phase C: s1[c] += p[r] ----
#pragma unroll 2
    for (int i = tid; i < NE; i += nthread) {
        int r = row[i];
        int c = col[i];
        atomicAdd(&g_s1[c], __ldg(&g_p[r]));
    }
    gsync(base + 3);

    // ---- Phase D: s1 = dinv*(acc+p); h1 = relu(W1*s1+b1); p2 = (h1@W2)*dinv ----
    for (int i = tid; i < NN; i += nthread) {
        float dinv = g_dinv[i];
        float s1   = dinv * (g_s1[i] + g_p[i]);
        float a = 0.f, b = 0.f;
#pragma unroll 8
        for (int j = 0; j < HID; ++j) {
            float h = fmaxf(fmaf(sW1[j], s1, sb1[j]), 0.f);
            a = fmaf(h, sW2[2 * j],     a);
            b = fmaf(h, sW2[2 * j + 1], b);
        }
        g_p2[i] = make_float2(a * dinv, b * dinv);
    }
    gsync(base + 4);

    // ---- Phase E: acc[c] += p2[r] (float2 vector atomic) ----
#pragma unroll 2
    for (int i = tid; i < NE; i += nthread) {
        int r = row[i];
        int c = col[i];
        float2 v = *reinterpret_cast<const float2*>(&g_p2[r]);
        atomicAdd(&g_acc[c], v);
    }
    gsync(base + 5);

    // ---- Phase F: out = dinv*(acc+p2) + b2 ; reset scratch for next replay ----
    for (int i = tid; i < NN; i += nthread) {
        float dinv = g_dinv[i];
        float2 acc = g_acc[i];
        float2 p2  = g_p2[i];
        float2 o;
        o.x = fmaf(dinv, acc.x + p2.x, b2[0]);
        o.y = fmaf(dinv, acc.y + p2.y, b2[1]);
        reinterpret_cast<float2*>(out)[i] = o;

        g_deg[i] = 0;
        g_s1[i]  = 0.f;
        g_acc[i] = make_float2(0.f, 0.f);
    }
}

extern "C" void kernel_launch(void* const* d_in, const int* in_sizes, int n_in,
                              void* d_out, int out_size) {
    const float* x   = (const float*)d_in[0];
    const int*   ei  = (const int*)d_in[1];   // [2, NE]: row then col
    const float* W1  = (const float*)d_in[2];
    const float* b1  = (const float*)d_in[3];
    const float* W2  = (const float*)d_in[4];
    const float* b2  = (const float*)d_in[5];
    float* out = (float*)d_out;

    const int* row = ei;
    const int* col = ei + NE;

    // Never launch more blocks than can be co-resident (barrier safety).
    int nblk = NBLK_MAX;
    int dev = 0, nsm = 0, per_sm = 0;
    if (cudaGetDevice(&dev) == cudaSuccess &&
        cudaDeviceGetAttribute(&nsm, cudaDevAttrMultiProcessorCount, dev) == cudaSuccess &&
        cudaOccupancyMaxActiveBlocksPerMultiprocessor(&per_sm, gcn_fused, TB, 0) == cudaSuccess &&
        nsm > 0 && per_sm > 0) {
        int cap = nsm * per_sm;
        if (cap < nblk) nblk = cap;
    }

    gcn_fused<<<nblk, TB>>>(x, row, col, W1, b1, W2, b2, out);
}

// round 12
// speedup vs baseline: 1.3624x; 1.2090x over previous
#include <cuda_runtime.h>

// GCN_12867722019091 — 2-layer GCN, N=50000, E=800000, HID=64, OUT=2.
// Split PDL chain (R7 structure, 32.8us) + smem-gather scatter kernels:
// the divergent gather (2.07 cyc/lane via L1tex) moves to shared memory
// (whole g_p table fits in 195KB smem/SM), leaving only the RED lanes.

constexpr int NN  = 50000;
constexpr int NE  = 800000;
constexpr int HID = 64;
constexpr int HALF = 25000;           // scat2 half-range

__device__ int    g_deg[NN];
__device__ float  g_dinv[NN];
__device__ float  g_p[NN];      // x[n] * dinv[n]
__device__ float  g_s1[NN];     // layer-1 scalar scatter accumulator
__device__ float2 g_p2[NN];     // g[n,:] * dinv[n]
__device__ float2 g_acc[NN];    // layer-2 float2 scatter accumulator

__device__ __forceinline__ void pdl_wait() {
#if __CUDA_ARCH__ >= 900
    asm volatile("griddepcontrol.wait;" ::: "memory");
#endif
}
__device__ __forceinline__ void pdl_trigger() {
#if __CUDA_ARCH__ >= 900
    asm volatile("griddepcontrol.launch_dependents;" ::: "memory");
#endif
}

// ---- edge pass 1: in-degree count (1 edge/thread, proven config) ----
__global__ void __launch_bounds__(256) k_count(const int* __restrict__ col) {
    int i = blockIdx.x * blockDim.x + threadIdx.x;
    int c = (i < NE) ? col[i] : 0;               // prologue (safe pre-wait)
    pdl_wait();                                   // prev replay's reset done
    pdl_trigger();
    if (i < NE) atomicAdd(&g_deg[c], 1);
}

// ---- node pass 1: dinv = rsqrt(deg+1); p = x*dinv ----
__global__ void __launch_bounds__(256) k_node1(const float* __restrict__ x) {
    int i = blockIdx.x * blockDim.x + threadIdx.x;
    float xv = (i < NN) ? x[i] : 0.f;             // prologue
    pdl_wait();                                   // g_deg ready
    pdl_trigger();
    if (i >= NN) return;
    float dinv = rsqrtf((float)(g_deg[i] + 1));
    g_dinv[i] = dinv;
    g_p[i]    = xv * dinv;
}

// ---- edge pass 2: s1[c] += p[r], gather from smem ----
__global__ void __launch_bounds__(1024) k_scat1(const int* __restrict__ row,
                                                const int* __restrict__ col) {
    extern __shared__ float sp[];                 // NN floats (195.3 KB)
    pdl_wait();                                   // g_p ready
    const int t  = threadIdx.x;
    const int nt = gridDim.x * 1024;
    // fill: whole p table into smem (coalesced, L2-resident source)
    for (int i = t; i < NN; i += 1024) sp[i] = g_p[i];
    __syncthreads();
    pdl_trigger();
    for (int i = blockIdx.x * 1024 + t; i < NE; i += nt) {
        int r = row[i];
        int c = col[i];
        atomicAdd(&g_s1[c], sp[r]);
    }
}

// ---- node pass 2: s1 = dinv*(acc+p); h1 = relu(W1*s1+b1); p2 = (h1@W2)*dinv ----
__global__ void __launch_bounds__(256) k_node2(const float* __restrict__ W1,
                                               const float* __restrict__ b1,
                                               const float* __restrict__ W2) {
    __shared__ float sW1[HID], sb1[HID], sW2[HID * 2];
    int t = threadIdx.x;
    if (t < HID)     { sW1[t] = W1[t]; sb1[t] = b1[t]; }   // prologue
    if (t < HID * 2) { sW2[t] = W2[t]; }
    __syncthreads();
    pdl_wait();                                   // g_s1 ready
    pdl_trigger();

    int i = blockIdx.x * blockDim.x + t;
    if (i >= NN) return;
    float dinv = g_dinv[i];
    float s1   = dinv * (g_s1[i] + g_p[i]);
    float a = 0.f, b = 0.f;
#pragma unroll
    for (int j = 0; j < HID; ++j) {
        float h = fmaxf(fmaf(sW1[j], s1, sb1[j]), 0.f);
        a = fmaf(h, sW2[2 * j],     a);
        b = fmaf(h, sW2[2 * j + 1], b);
    }
    g_p2[i] = make_float2(a * dinv, b * dinv);
}

// ---- edge pass 3: acc[c] += p2[r], two half-range smem passes ----
__global__ void __launch_bounds__(1024) k_scat2(const int* __restrict__ row,
                                                const int* __restrict__ col) {
    extern __shared__ float2 sp2[];               // HALF float2 (195.3 KB)
    pdl_wait();                                   // g_p2 ready
    const int t   = threadIdx.x;
    const int gtid = blockIdx.x * 1024 + t;
    const int nt  = gridDim.x * 1024;

    // pass 0: nodes [0, HALF)
    for (int i = t; i < HALF; i += 1024) sp2[i] = g_p2[i];
    __syncthreads();
    pdl_trigger();
    for (int i = gtid; i < NE; i += nt) {
        int r = row[i];
        int c = col[i];
        if (r < HALF) atomicAdd(&g_acc[c], sp2[r]);
    }
    __syncthreads();

    // pass 1: nodes [HALF, NN)
    for (int i = t; i < NN - HALF; i += 1024) sp2[i] = g_p2[HALF + i];
    __syncthreads();
    for (int i = gtid; i < NE; i += nt) {
        int r = row[i];
        int c = col[i];
        if (r >= HALF) atomicAdd(&g_acc[c], sp2[r - HALF]);
    }
}

// ---- final: out = dinv*(acc+p2) + b2 ; reset scratch ----
__global__ void __launch_bounds__(256) k_final(float* __restrict__ out,
                                               const float* __restrict__ b2) {
    int i = blockIdx.x * blockDim.x + threadIdx.x;
    float b2x = b2[0], b2y = b2[1];               // prologue
    pdl_wait();                                   // g_acc ready
    pdl_trigger();
    if (i >= NN) return;
    float dinv = g_dinv[i];
    float2 acc = g_acc[i];
    float2 p2  = g_p2[i];
    float2 o;
    o.x = fmaf(dinv, acc.x + p2.x, b2x);
    o.y = fmaf(dinv, acc.y + p2.y, b2y);
    reinterpret_cast<float2*>(out)[i] = o;

    g_deg[i] = 0;
    g_s1[i]  = 0.f;
    g_acc[i] = make_float2(0.f, 0.f);
}

// ---- host ----

static void launch_pdl(const void* fn, int grid, int block, void** args,
                       size_t smem = 0) {
    cudaLaunchConfig_t cfg = {};
    cfg.gridDim  = dim3(grid, 1, 1);
    cfg.blockDim = dim3(block, 1, 1);
    cfg.dynamicSmemBytes = smem;
    cfg.stream   = 0;
    cudaLaunchAttribute attr[1];
    attr[0].id = cudaLaunchAttributeProgrammaticStreamSerialization;
    attr[0].val.programmaticStreamSerializationAllowed = 1;
    cfg.attrs    = attr;
    cfg.numAttrs = 1;
    cudaLaunchKernelExC(&cfg, fn, args);
}

extern "C" void kernel_launch(void* const* d_in, const int* in_sizes, int n_in,
                              void* d_out, int out_size) {
    const float* x   = (const float*)d_in[0];
    const int*   ei  = (const int*)d_in[1];   // [2, NE]
    const float* W1  = (const float*)d_in[2];
    const float* b1  = (const float*)d_in[3];
    const float* W2  = (const float*)d_in[4];
    const float* b2  = (const float*)d_in[5];
    float* out = (float*)d_out;

    const int* row = ei;
    const int* col = ei + NE;

    const size_t SM1 = (size_t)NN * sizeof(float);      // 200000 B
    const size_t SM2 = (size_t)HALF * sizeof(float2);   // 200000 B

    static bool attr_done = false;
    if (!attr_done) {
        cudaFuncSetAttribute(k_scat1, cudaFuncAttributeMaxDynamicSharedMemorySize, (int)SM1);
        cudaFuncSetAttribute(k_scat2, cudaFuncAttributeMaxDynamicSharedMemorySize, (int)SM2);
        attr_done = true;
    }

    int dev = 0, nsm = 148;
    cudaGetDevice(&dev);
    cudaDeviceGetAttribute(&nsm, cudaDevAttrMultiProcessorCount, dev);

    const int TB = 256;
    const int nodeBlocks = (NN + TB - 1) / TB;
    const int edgeBlocks = (NE + TB - 1) / TB;

    { void* a[] = { (void*)&col };                        launch_pdl((const void*)k_count, edgeBlocks, TB, a); }
    { void* a[] = { (void*)&x };                          launch_pdl((const void*)k_node1, nodeBlocks, TB, a); }
    { void* a[] = { (void*)&row, (void*)&col };           launch_pdl((const void*)k_scat1, nsm, 1024, a, SM1); }
    { void* a[] = { (void*)&W1, (void*)&b1, (void*)&W2 }; launch_pdl((const void*)k_node2, nodeBlocks, TB, a); }
    { void* a[] = { (void*)&row, (void*)&col };           launch_pdl((const void*)k_scat2, nsm, 1024, a, SM2); }
    { void* a[] = { (void*)&out, (void*)&b2 };            launch_pdl((const void*)k_final, nodeBlocks, TB, a); }
}